// round 14
// baseline (speedup 1.0000x reference)
#include <cuda_runtime.h>

#define BATCH  4096
#define TSTEPS 100
#define DDIM   100
#define OOUT   3
#define CW     (BATCH * OOUT)

#define FPSCALE 67108864.0f                       /* 2^26 */
#define INV_FPSCALE 1.490116119384765625e-8f      /* 2^-26 */

// Scratch: cur[t][b*3+c] = spikes(b,t,:).W[c,:] + bias[c]  (4.9 MB, L2-resident)
__device__ float g_cur[TSTEPS * CW];

// ---------------- K1: pure-streaming dot products --------------------------
// grid (50, 1024), block 128: warp w of block (p, bg) handles batch 4*bg+w,
// rows 2p and 2p+1. No serial loop, no cross-warp coupling.
__global__ __launch_bounds__(128) void cur_kernel(
    const float* __restrict__ x, const float* __restrict__ u,
    const float* __restrict__ W, const float* __restrict__ bias)
{
    __shared__ int4 lut[16 * 32];   // LUT[mask][lane] = fixed-point subset sums

    for (int e = threadIdx.x; e < 16 * 32; e += 128) {
        const int mask = e >> 5;
        const int ln   = e & 31;
        int s0 = 0, s1 = 0, s2 = 0;
        if (ln < (DDIM / 4)) {
            #pragma unroll
            for (int bit = 0; bit < 4; ++bit) {
                if ((mask >> bit) & 1) {
                    const int col = ln * 4 + bit;
                    s0 += __float2int_rn(__ldg(W + 0 * DDIM + col) * FPSCALE);
                    s1 += __float2int_rn(__ldg(W + 1 * DDIM + col) * FPSCALE);
                    s2 += __float2int_rn(__ldg(W + 2 * DDIM + col) * FPSCALE);
                }
            }
        }
        lut[(mask << 5) | ln] = make_int4(s0, s1, s2, 0);
    }
    __syncthreads();

    const int wid  = threadIdx.x >> 5;
    const int lane = threadIdx.x & 31;
    const int b    = (blockIdx.y << 2) | wid;   // batch id
    const int t0   = blockIdx.x * 2;            // first of this warp's 2 rows
    const bool act = (lane < (DDIM / 4));

    const float bl = __ldg(bias + ((lane < 2) ? lane : 2));

    const float4 z = make_float4(0.f, 0.f, 0.f, 0.f);
    const float4* __restrict__ xr =
        (const float4*)(x + (size_t)b * (TSTEPS * DDIM) + (size_t)t0 * DDIM);
    const float4* __restrict__ ur =
        (const float4*)(u + (size_t)b * (TSTEPS * DDIM) + (size_t)t0 * DDIM);

    float4 xa = z, ua = z, xb = z, ub = z;
    if (act) {
        xa = xr[lane];              ua = ur[lane];
        xb = xr[lane + (DDIM / 4)]; ub = ur[lane + (DDIM / 4)];
    }

    const int ma = (ua.x < xa.x) | ((ua.y < xa.y) << 1)
                 | ((ua.z < xa.z) << 2) | ((ua.w < xa.w) << 3);
    const int mb = (ub.x < xb.x) | ((ub.y < xb.y) << 1)
                 | ((ub.z < xb.z) << 2) | ((ub.w < xb.w) << 3);

    const int4 la = lut[(ma << 5) | lane];
    const int4 lb = lut[(mb << 5) | lane];

    const int sa0 = __reduce_add_sync(0xffffffffu, la.x);
    const int sb0 = __reduce_add_sync(0xffffffffu, lb.x);
    const int sa1 = __reduce_add_sync(0xffffffffu, la.y);
    const int sb1 = __reduce_add_sync(0xffffffffu, lb.y);
    const int sa2 = __reduce_add_sync(0xffffffffu, la.z);
    const int sb2 = __reduce_add_sync(0xffffffffu, lb.z);

    if (lane < OOUT) {
        const int ia = (lane == 0) ? sa0 : ((lane == 1) ? sa1 : sa2);
        const int ib = (lane == 0) ? sb0 : ((lane == 1) ? sb1 : sb2);
        const size_t o = (size_t)b * OOUT + lane;
        g_cur[(size_t)t0 * CW + o]       = (float)ia * INV_FPSCALE + bl;
        g_cur[(size_t)(t0 + 1) * CW + o] = (float)ib * INV_FPSCALE + bl;
    }
}

// ---------------- K2: leaky scan, thread per (b, chan), chunked pipeline ----
__global__ __launch_bounds__(128) void scan_kernel(
    const float* __restrict__ betap, const float* __restrict__ thrp,
    float* __restrict__ out)
{
    const int tid = blockIdx.x * blockDim.x + threadIdx.x;   // 0..12287 (grid exact)

    const float beta = __ldg(betap);
    const float thr  = __ldg(thrp);

    float* __restrict__ spk = out;
    float* __restrict__ mem = out + (size_t)TSTEPS * CW;

    float bufA[10], bufB[10];

    // prologue: chunk 0
    #pragma unroll
    for (int k = 0; k < 10; ++k) bufA[k] = g_cur[(size_t)k * CW + tid];

    float m = 0.f, r = 0.f;

    #pragma unroll
    for (int c = 0; c < 10; ++c) {
        float* curb = (c & 1) ? bufB : bufA;
        float* nxtb = (c & 1) ? bufA : bufB;

        // prefetch chunk c+1 (independent of scan chain)
        if (c < 9) {
            #pragma unroll
            for (int k = 0; k < 10; ++k)
                nxtb[k] = g_cur[(size_t)((c + 1) * 10 + k) * CW + tid];
        }

        #pragma unroll
        for (int k = 0; k < 10; ++k) {
            const int t = c * 10 + k;
            m = beta * m + curb[k] - r;
            const float sp = (m - thr > 0.f) ? 1.f : 0.f;
            r = sp * thr;
            const size_t o = (size_t)t * CW + tid;
            __stcs(spk + o, sp);
            __stcs(mem + o, m);
        }
    }
}

extern "C" void kernel_launch(void* const* d_in, const int* in_sizes, int n_in,
                              void* d_out, int out_size)
{
    const float* x    = (const float*)d_in[0];
    const float* u    = (const float*)d_in[1];
    const float* W    = (const float*)d_in[2];
    const float* bias = (const float*)d_in[3];
    const float* beta = (const float*)d_in[4];
    const float* thr  = (const float*)d_in[5];
    float* out = (float*)d_out;

    dim3 g1(TSTEPS / 2, BATCH / 4);          // (50, 1024)
    cur_kernel<<<g1, 128>>>(x, u, W, bias);

    scan_kernel<<<CW / 128, 128>>>(beta, thr, out);   // 96 blocks
}

// round 15
// speedup vs baseline: 1.8797x; 1.8797x over previous
#include <cuda_runtime.h>

#define BATCH  4096
#define TSTEPS 100
#define DDIM   100
#define OOUT   3
#define CW     (BATCH * OOUT)

#define FPSCALE 67108864.0f                       /* 2^26 */
#define INV_FPSCALE 1.490116119384765625e-8f      /* 2^-26 */

#define RPW    25    /* rows per streaming warp */
#define NPAIR  13    /* 12 full pairs + 1 clamped pair covering row 24 */

// Block of 8 warps owns 2 batch elements. Phase 1: warps 0-3 stream batch A's
// 100 rows (25 each), warps 4-7 batch B; int dot-sums (mask->LUT->REDUX) go to
// smem. One __syncthreads. Phase 2: warps 0 and 4 (lanes 0-2) scan 100 steps
// from smem and store. Int sums identical to R12 -> bit-identical outputs.
__global__ __launch_bounds__(256, 8) void leaky_block(
    const float* __restrict__ x, const float* __restrict__ u,
    const float* __restrict__ W, const float* __restrict__ bias,
    const float* __restrict__ betap, const float* __restrict__ thrp,
    float* __restrict__ out)
{
    __shared__ int4 lut[16 * 32];            // 8 KB
    __shared__ int  sums[2][TSTEPS][OOUT];   // 2.4 KB

    // LUT[mask][lane] = fixed-point subset sums of lane's 4 weight columns
    for (int e = threadIdx.x; e < 16 * 32; e += 256) {
        const int mask = e >> 5;
        const int ln   = e & 31;
        int s0 = 0, s1 = 0, s2 = 0;
        if (ln < (DDIM / 4)) {
            #pragma unroll
            for (int bit = 0; bit < 4; ++bit) {
                if ((mask >> bit) & 1) {
                    const int col = ln * 4 + bit;
                    s0 += __float2int_rn(__ldg(W + 0 * DDIM + col) * FPSCALE);
                    s1 += __float2int_rn(__ldg(W + 1 * DDIM + col) * FPSCALE);
                    s2 += __float2int_rn(__ldg(W + 2 * DDIM + col) * FPSCALE);
                }
            }
        }
        lut[(mask << 5) | ln] = make_int4(s0, s1, s2, 0);
    }
    __syncthreads();

    const int wid  = threadIdx.x >> 5;      // 0..7
    const int lane = threadIdx.x & 31;
    const int bsel = wid >> 2;              // batch within block (0/1)
    const int wseg = wid & 3;               // row segment (0..3)
    const int b    = (blockIdx.x << 1) | bsel;
    const int r0   = wseg * RPW;            // first row of this warp's segment
    const bool act = (lane < (DDIM / 4));   // 25 active load lanes

    const float4 z = make_float4(0.f, 0.f, 0.f, 0.f);
    const float4* __restrict__ xr =
        (const float4*)(x + (size_t)b * (TSTEPS * DDIM) + (size_t)r0 * DDIM);
    const float4* __restrict__ ur =
        (const float4*)(u + (size_t)b * (TSTEPS * DDIM) + (size_t)r0 * DDIM);

    // ---------------- phase 1: stream 25 rows as 13 (clamped) pairs ---------
    // pair p covers local rows (2p, min(2p+1, 24)); last pair re-reads row 24.
    float4 xa = z, ua = z, xb = z, ub = z;
    if (act) {
        xa = xr[lane];              ua = ur[lane];
        xb = xr[lane + (DDIM / 4)]; ub = ur[lane + (DDIM / 4)];
    }

    for (int p = 0; p < NPAIR; ++p) {
        // prefetch pair p+1 (clamped second row)
        float4 nxa = z, nua = z, nxb = z, nub = z;
        if (act && (p + 1 < NPAIR)) {
            const int ra = 2 * (p + 1);
            const int rb = (ra + 1 < RPW) ? ra + 1 : ra;
            nxa = xr[ra * (DDIM / 4) + lane];  nua = ur[ra * (DDIM / 4) + lane];
            nxb = xr[rb * (DDIM / 4) + lane];  nub = ur[rb * (DDIM / 4) + lane];
        }

        const int ma = (ua.x < xa.x) | ((ua.y < xa.y) << 1)
                     | ((ua.z < xa.z) << 2) | ((ua.w < xa.w) << 3);
        const int mb = (ub.x < xb.x) | ((ub.y < xb.y) << 1)
                     | ((ub.z < xb.z) << 2) | ((ub.w < xb.w) << 3);

        const int4 la = lut[(ma << 5) | lane];
        const int4 lb = lut[(mb << 5) | lane];
        const int sa0 = __reduce_add_sync(0xffffffffu, la.x);
        const int sb0 = __reduce_add_sync(0xffffffffu, lb.x);
        const int sa1 = __reduce_add_sync(0xffffffffu, la.y);
        const int sb1 = __reduce_add_sync(0xffffffffu, lb.y);
        const int sa2 = __reduce_add_sync(0xffffffffu, la.z);
        const int sb2 = __reduce_add_sync(0xffffffffu, lb.z);

        if (lane < OOUT) {
            const int va = (lane == 0) ? sa0 : ((lane == 1) ? sa1 : sa2);
            const int vb = (lane == 0) ? sb0 : ((lane == 1) ? sb1 : sb2);
            const int ra = 2 * p;
            sums[bsel][r0 + ra][lane] = va;
            if (ra + 1 < RPW) sums[bsel][r0 + ra + 1][lane] = vb;
        }

        xa = nxa; ua = nua; xb = nxb; ub = nub;
    }

    __syncthreads();   // the ONLY cross-warp sync

    // ---------------- phase 2: serial leaky scan (warps 0 and 4) ------------
    if (wseg == 0 && lane < OOUT) {
        const float beta = __ldg(betap);
        const float thr  = __ldg(thrp);
        const float bl   = __ldg(bias + lane);

        float* __restrict__ spk = out;
        float* __restrict__ mem = out + (size_t)TSTEPS * CW;
        const size_t obase = (size_t)b * OOUT + lane;

        float m = 0.f, r = 0.f;
        #pragma unroll 10
        for (int t = 0; t < TSTEPS; ++t) {
            const float cur = (float)sums[bsel][t][lane] * INV_FPSCALE + bl;
            m = beta * m + cur - r;
            const float sp = (m - thr > 0.f) ? 1.f : 0.f;
            r = sp * thr;
            const size_t o = (size_t)t * CW + obase;
            __stcs(spk + o, sp);
            __stcs(mem + o, m);
        }
    }
}

extern "C" void kernel_launch(void* const* d_in, const int* in_sizes, int n_in,
                              void* d_out, int out_size)
{
    const float* x    = (const float*)d_in[0];
    const float* u    = (const float*)d_in[1];
    const float* W    = (const float*)d_in[2];
    const float* bias = (const float*)d_in[3];
    const float* beta = (const float*)d_in[4];
    const float* thr  = (const float*)d_in[5];
    float* out = (float*)d_out;

    leaky_block<<<BATCH / 2, 256>>>(x, u, W, bias, beta, thr, out);
}